// round 6
// baseline (speedup 1.0000x reference)
#include <cuda_runtime.h>
#include <cuda_bf16.h>
#include <cstdint>

#define HH 224
#define WW 224
#define HW (HH*WW)
#define OH 448
#define OW 448
#define OHW (OH*OW)

typedef unsigned int u32;
typedef unsigned long long u64;

// ---------------------------------------------------------------------------
// Scratch: activations pixel-major packed (bf16 hi | bf16 lo<<16)
// ---------------------------------------------------------------------------
__device__ u32  act2_x0[HW * 100];
__device__ u32  act2_feats[5 * HW * 100];
__device__ float g_x36[36 * HW];
__device__ float g_smn[2 * HW];
// weight images: [5 layers][9 kpos][2 splits][128 oc x 120 ci-stride] bf16
__device__ __align__(16) __nv_bfloat16 g_wimg[5 * 9 * 2 * 15360];

// ---------------------------------------------------------------------------
// helpers
// ---------------------------------------------------------------------------
__device__ __forceinline__ u32 smem_u32(const void* p) {
    u32 r;
    asm("{ .reg .u64 t; cvta.to.shared.u64 t, %1; cvt.u32.u64 %0, t; }"
        : "=r"(r) : "l"(p));
    return r;
}
__device__ __forceinline__ void cp16(u32 dst, const void* src) {
    asm volatile("cp.async.cg.shared.global [%0], [%1], 16;"
                 :: "r"(dst), "l"(src));
}
__device__ __forceinline__ void cp_commit() { asm volatile("cp.async.commit_group;"); }
__device__ __forceinline__ void cp_wait0()  { asm volatile("cp.async.wait_group 0;"); }
__device__ __forceinline__ void cp_wait1()  { asm volatile("cp.async.wait_group 1;"); }

__device__ __forceinline__ void ldsm4(u32* r, u32 addr) {
    asm volatile("ldmatrix.sync.aligned.m8n8.x4.shared.b16 {%0,%1,%2,%3}, [%4];"
        : "=r"(r[0]), "=r"(r[1]), "=r"(r[2]), "=r"(r[3]) : "r"(addr));
}
__device__ __forceinline__ void mma16816(float* c, const u32* a, u32 b0, u32 b1) {
    asm volatile("mma.sync.aligned.m16n8k16.row.col.f32.bf16.bf16.f32 "
        "{%0,%1,%2,%3}, {%4,%5,%6,%7}, {%8,%9}, {%0,%1,%2,%3};"
        : "+f"(c[0]), "+f"(c[1]), "+f"(c[2]), "+f"(c[3])
        : "r"(a[0]), "r"(a[1]), "r"(a[2]), "r"(a[3]), "r"(b0), "r"(b1));
}

// pack/unpack fp32 <-> (bf16 hi in low16 | bf16 lo in high16)
__device__ __forceinline__ u32 pack_hl(float v) {
    __nv_bfloat16 h = __float2bfloat16(v);
    float fh = __bfloat162float(h);
    __nv_bfloat16 l = __float2bfloat16(v - fh);
    return (u32)__bfloat16_as_ushort(h) | ((u32)__bfloat16_as_ushort(l) << 16);
}
__device__ __forceinline__ float unpack_hl(u32 b) {
    return __uint_as_float(b << 16) + __uint_as_float(b & 0xFFFF0000u);
}

// f32x2
__device__ __forceinline__ u64 pack2f(float lo, float hi) {
    u64 r; asm("mov.b64 %0, {%1, %2};" : "=l"(r) : "f"(lo), "f"(hi)); return r;
}
__device__ __forceinline__ void unpack2f(u64 v, float& lo, float& hi) {
    asm("mov.b64 {%0, %1}, %2;" : "=f"(lo), "=f"(hi) : "l"(v));
}
__device__ __forceinline__ void ffma2(u64& acc, u64 a, u64 b) {
    asm("fma.rn.f32x2 %0, %1, %2, %0;" : "+l"(acc) : "l"(a), "l"(b));
}

// ---------------------------------------------------------------------------
// Prep: weight images. grid = 45 (layer*9 + kpos)
// Per kpos: hi split [128x120] then lo split, row-major, 120-elem ci stride.
// ---------------------------------------------------------------------------
__global__ __launch_bounds__(256) void prep_weights_kernel(
    const float* __restrict__ w_head, const float* __restrict__ w_blocks)
{
    int l = blockIdx.x / 9, kp = blockIdx.x - 9 * (blockIdx.x / 9);
    const float* src = (l == 0) ? w_head : (w_blocks + (l - 1) * 90000);
    __nv_bfloat16* dhi = g_wimg + (size_t)(l * 9 + kp) * 30720;
    __nv_bfloat16* dlo = dhi + 15360;
    for (int i = threadIdx.x; i < 15360; i += 256) {
        int m = i / 120, k = i - 120 * (i / 120);
        float wv = (m < 100 && k < 100) ? src[m * 900 + k * 9 + kp] : 0.f;
        __nv_bfloat16 h = __float2bfloat16(wv);
        __nv_bfloat16 lo = __float2bfloat16(wv - __bfloat162float(h));
        dhi[i] = h;
        dlo[i] = lo;
    }
}

// ---------------------------------------------------------------------------
// Kernel 1: warp + concat -> act2_x0 [p][100]
// ---------------------------------------------------------------------------
__global__ __launch_bounds__(256) void warp_concat_kernel(
    const float* __restrict__ f0, const float* __restrict__ f1,
    const float* __restrict__ fd, const float* __restrict__ flow)
{
    int p = blockIdx.x * 256 + threadIdx.x;
    if (p >= HW) return;
    int y = p / WW, x = p - y * WW;
    u32* row = act2_x0 + (size_t)p * 100;

    #pragma unroll 4
    for (int c = 0; c < 32; c++) row[64 + c] = pack_hl(fd[c * HW + p]);
    #pragma unroll
    for (int c = 0; c < 4; c++)  row[96 + c] = pack_hl(flow[c * HW + p]);

    #pragma unroll
    for (int pair = 0; pair < 2; pair++) {
        const float* img = (pair == 0) ? f0 : f1;
        float px = (float)x + flow[(pair * 2 + 0) * HW + p];
        float py = (float)y + flow[(pair * 2 + 1) * HW + p];
        float fx = floorf(px), fy = floorf(py);
        float wx = px - fx, wy = py - fy;
        int ix = (int)fminf(fmaxf(fx, -2.f), 226.f);
        int iy = (int)fminf(fmaxf(fy, -2.f), 226.f);
        int x0i = min(max(ix, 0), WW - 1);
        int x1i = min(max(ix + 1, 0), WW - 1);
        int y0i = min(max(iy, 0), HH - 1);
        int y1i = min(max(iy + 1, 0), HH - 1);
        float w00 = (1.f - wx) * (1.f - wy);
        float w01 = wx * (1.f - wy);
        float w10 = (1.f - wx) * wy;
        float w11 = wx * wy;
        int b00 = y0i * WW + x0i, b01 = y0i * WW + x1i;
        int b10 = y1i * WW + x0i, b11 = y1i * WW + x1i;
        #pragma unroll 4
        for (int c = 0; c < 32; c++) {
            const float* g = img + c * HW;
            float v = g[b00] * w00 + g[b01] * w01 + g[b10] * w10 + g[b11] * w11;
            row[pair * 32 + c] = pack_hl(v);
        }
    }
}

// ---------------------------------------------------------------------------
// Kernel 2: HMMA implicit-GEMM 3x3 conv.
// CTA: 128 px x 128 oc (100 used). 8 warps = 2 m-groups (4 m-tiles) x
// 4 px-groups (32 px = 4 n-fragments). Split bf16 hi/lo, 3 products.
// ---------------------------------------------------------------------------
#define WSTRIDE 240       // A smem row stride bytes (120 halves)
#define SPLIT_B 30720     // bytes per split (128 x 240)
#define KPOS_B  61440     // bytes per kpos stage
#define CONV_DSMEM (2 * KPOS_B)

__device__ __forceinline__ void loadB1(u32* b, const u32* r, bool ok, int ci) {
    u32 v0 = 0, v1 = 0, w0 = 0, w1 = 0;
    if (ok && ci <= 98)     { uint2 t = *(const uint2*)(r + ci);     v0 = t.x; v1 = t.y; }
    if (ok && ci + 8 <= 98) { uint2 t = *(const uint2*)(r + ci + 8); w0 = t.x; w1 = t.y; }
    b[0] = __byte_perm(v0, v1, 0x5410);  // hi pair k,k+1
    b[1] = __byte_perm(w0, w1, 0x5410);  // hi pair k+8,k+9
    b[2] = __byte_perm(v0, v1, 0x7632);  // lo pair
    b[3] = __byte_perm(w0, w1, 0x7632);
}

template <int MODE>
__global__ __launch_bounds__(256) void conv_hmma_kernel(
    const u32* __restrict__ in,                 // [HW][100]
    const __nv_bfloat16* __restrict__ wimg,     // layer base, [9][2][15360]
    const float* __restrict__ aux,
    const float* __restrict__ mask,
    u32* __restrict__ outp)                     // [HW][100]
{
    extern __shared__ __align__(16) char dsm[];
    __shared__ float s_mask[128];
    __shared__ float s_aux[128];

    const int tid = threadIdx.x;
    const int w = tid >> 5;
    const int lid = tid & 31;
    const int mg = w >> 2;           // m-group 0/1
    const int pg = w & 3;            // px-group 0..3
    const int pixbase = blockIdx.x << 7;

    if (tid < 128) s_mask[tid] = mask[pixbase + tid];
    if (tid < 128) s_aux[tid] = (tid < 100) ? aux[tid] : 0.f;

    const u32 sb = smem_u32(dsm);

    // pixel coords for the 4 n-fragments of this warp
    int pyv[4], pxv[4];
    #pragma unroll
    for (int nf = 0; nf < 4; nf++) {
        int p = pixbase + pg * 32 + nf * 8 + (lid >> 2);
        pyv[nf] = p / WW;
        pxv[nf] = p - pyv[nf] * WW;
    }

    float acc[4][4][4];
    #pragma unroll
    for (int m = 0; m < 4; m++)
        #pragma unroll
        for (int nf = 0; nf < 4; nf++)
            #pragma unroll
            for (int i = 0; i < 4; i++) acc[m][nf][i] = 0.f;

    // prologue: stage kpos 0 into buf 0 (3840 x 16B)
    {
        const char* src = (const char*)wimg;
        for (int i = tid; i < 3840; i += 256) cp16(sb + i * 16, src + i * 16);
        cp_commit();
    }

    const int cib = (lid & 3) * 2;
    const u32 arow = (u32)(mg * 64 + (lid & 15)) * WSTRIDE + (lid >> 4) * 16;

    for (int kp = 0; kp < 9; kp++) {
        const int buf = kp & 1;
        const u32 bufaddr = sb + buf * KPOS_B;

        if (kp < 8) {
            const char* src = (const char*)wimg + (size_t)(kp + 1) * KPOS_B;
            u32 dst = sb + (buf ^ 1) * KPOS_B;
            for (int i = tid; i < 3840; i += 256) cp16(dst + i * 16, src + i * 16);
            cp_commit();
            cp_wait1();
        } else {
            cp_wait0();
        }
        __syncthreads();

        const int ky = kp / 3, kx = kp - 3 * (kp / 3);
        const u32* rws[4];
        bool oks[4];
        #pragma unroll
        for (int nf = 0; nf < 4; nf++) {
            int iy = pyv[nf] + ky - 1, ix = pxv[nf] + kx - 1;
            oks[nf] = (iy >= 0) & (iy < HH) & (ix >= 0) & (ix < WW);
            rws[nf] = in + (size_t)(iy * WW + ix) * 100;
        }

        u32 bc[16], bn[16];
        #pragma unroll
        for (int nf = 0; nf < 4; nf++)
            loadB1(bc + nf * 4, rws[nf], oks[nf], cib);

        #pragma unroll
        for (int ks = 0; ks < 7; ks++) {
            if (ks < 6) {
                #pragma unroll
                for (int nf = 0; nf < 4; nf++)
                    loadB1(bn + nf * 4, rws[nf], oks[nf], cib + (ks + 1) * 16);
            }
            const u32 kaddr = bufaddr + arow + ks * 32;
            #pragma unroll
            for (int m = 0; m < 4; m++) {
                u32 ah[4], al[4];
                ldsm4(ah, kaddr + m * (16 * WSTRIDE));
                ldsm4(al, kaddr + m * (16 * WSTRIDE) + SPLIT_B);
                #pragma unroll
                for (int nf = 0; nf < 4; nf++) {
                    mma16816(acc[m][nf], ah, bc[nf * 4 + 0], bc[nf * 4 + 1]); // hh
                    mma16816(acc[m][nf], ah, bc[nf * 4 + 2], bc[nf * 4 + 3]); // h*l
                    mma16816(acc[m][nf], al, bc[nf * 4 + 0], bc[nf * 4 + 1]); // l*h
                }
            }
            #pragma unroll
            for (int q = 0; q < 16; q++) bc[q] = bn[q];
        }
        __syncthreads();
    }

    // epilogue: transform + smem transpose + coalesced store
    u32* tr = (u32*)dsm;      // [128 px][stride 116] u32
    #pragma unroll
    for (int m = 0; m < 4; m++) {
        const int oc0 = mg * 64 + m * 16 + (lid >> 2);
        #pragma unroll
        for (int nf = 0; nf < 4; nf++) {
            const int pxc = pg * 32 + nf * 8 + (lid & 3) * 2;
            #pragma unroll
            for (int i = 0; i < 4; i++) {
                const int oc = oc0 + (i >> 1) * 8;
                const int px = pxc + (i & 1);
                if (oc < 100) {
                    float v = acc[m][nf][i];
                    float a = s_aux[oc], mm = s_mask[px];
                    if (MODE == 0) {
                        v = (v >= 0.f ? v : a * v) * mm;
                    } else {
                        v *= mm;
                        v = (v >= 0.f ? v : a * v);
                    }
                    tr[px * 116 + oc] = pack_hl(v);
                }
            }
        }
    }
    __syncthreads();
    for (int i = tid; i < 12800; i += 256) {
        int px = i / 100, ci = i - 100 * (i / 100);
        outp[(size_t)(pixbase + px) * 100 + ci] = tr[px * 116 + ci];
    }
}

// ---------------------------------------------------------------------------
// Kernel 3: 1x1 conv 500 -> 36, f32x2, pixel-major packed input
// ---------------------------------------------------------------------------
__global__ __launch_bounds__(256) void conv1x1_kernel(
    const u32* __restrict__ feats, const float* __restrict__ wl,
    const float* __restrict__ bl, float* __restrict__ out)
{
    __shared__ __align__(16) float s_w[3600];
    const int tid = threadIdx.x;
    const size_t p = (size_t)blockIdx.x * 256 + tid;

    u64 acc[18];
    #pragma unroll
    for (int pr = 0; pr < 18; pr++) acc[pr] = pack2f(bl[pr * 2], bl[pr * 2 + 1]);

    for (int ch = 0; ch < 5; ch++) {
        __syncthreads();
        for (int i = tid; i < 3600; i += 256) {
            int ci = i / 36, o = i - ci * 36;
            s_w[(ci * 18 + (o >> 1)) * 2 + (o & 1)] = wl[o * 500 + ch * 100 + ci];
        }
        __syncthreads();
        const uint4* row = (const uint4*)(feats + ((size_t)ch * HW + p) * 100);
        #pragma unroll 5
        for (int g = 0; g < 25; g++) {
            uint4 q = row[g];
            u32 vv[4] = {q.x, q.y, q.z, q.w};
            #pragma unroll
            for (int j = 0; j < 4; j++) {
                float f = unpack_hl(vv[j]);
                u64 f2 = pack2f(f, f);
                const u64* wp = (const u64*)(s_w + (g * 4 + j) * 36);
                #pragma unroll
                for (int pr = 0; pr < 18; pr++) ffma2(acc[pr], wp[pr], f2);
            }
        }
    }
    #pragma unroll
    for (int pr = 0; pr < 18; pr++) {
        float v0, v1;
        unpack2f(acc[pr], v0, v1);
        out[(pr * 2 + 0) * HW + p] = v0;
        out[(pr * 2 + 1) * HW + p] = v1;
    }
}

// ---------------------------------------------------------------------------
// Kernel 2b: small 3x3 conv (mask head), 32 -> 2, bias
// ---------------------------------------------------------------------------
__global__ __launch_bounds__(256) void conv3x3_small_kernel(
    const float* __restrict__ in, const float* __restrict__ wgt,
    const float* __restrict__ bias, float* __restrict__ out)
{
    __shared__ float s_in[10 * 34];
    __shared__ float s_w[2 * 9];

    const int tid = threadIdx.x;
    const int tx = tid & 31;
    const int ty = tid >> 5;
    const int ox0 = blockIdx.x * 32;
    const int oy0 = blockIdx.y * 8;
    const int ox = ox0 + tx, oy = oy0 + ty;

    float acc0 = 0.f, acc1 = 0.f;

    for (int ci = 0; ci < 32; ci++) {
        #pragma unroll
        for (int idx = tid; idx < 340; idx += 256) {
            int r = idx / 34, c = idx - r * 34;
            int gy = oy0 - 1 + r, gx = ox0 - 1 + c;
            float v = 0.f;
            if (gx >= 0 && gx < WW && gy >= 0 && gy < HH)
                v = in[ci * HW + gy * WW + gx];
            s_in[idx] = v;
        }
        if (tid < 18)
            s_w[tid] = wgt[(tid / 9) * (32 * 9) + ci * 9 + (tid % 9)];
        __syncthreads();

        float r[9];
        #pragma unroll
        for (int ky = 0; ky < 3; ky++)
            #pragma unroll
            for (int kx = 0; kx < 3; kx++)
                r[ky * 3 + kx] = s_in[(ty + ky) * 34 + tx + kx];

        #pragma unroll
        for (int k = 0; k < 9; k++) {
            acc0 = fmaf(s_w[k], r[k], acc0);
            acc1 = fmaf(s_w[9 + k], r[k], acc1);
        }
        __syncthreads();
    }
    out[oy * WW + ox] = acc0 + bias[0];
    out[HW + oy * WW + ox] = acc1 + bias[1];
}

// ---------------------------------------------------------------------------
// Kernel 4: 2x bilinear upsample + mask
// ---------------------------------------------------------------------------
__global__ __launch_bounds__(256) void upsample_kernel(
    const float* __restrict__ x36, const float* __restrict__ smn,
    const float* __restrict__ smask, float* __restrict__ out)
{
    int p = blockIdx.x * 256 + threadIdx.x;
    if (p >= OHW) return;
    int oy = p / OW, ox = p - oy * OW;
    int iy = oy >> 1, ix = ox >> 1;

    int r0, r1; float wr0, wr1;
    if (oy & 1) { r0 = iy; r1 = min(iy + 1, HH - 1); wr0 = 0.75f; wr1 = 0.25f; }
    else        { r0 = max(iy - 1, 0); r1 = iy;      wr0 = 0.25f; wr1 = 0.75f; }
    int c0, c1; float wc0, wc1;
    if (ox & 1) { c0 = ix; c1 = min(ix + 1, WW - 1); wc0 = 0.75f; wc1 = 0.25f; }
    else        { c0 = max(ix - 1, 0); c1 = ix;      wc0 = 0.25f; wc1 = 0.75f; }

    int b00 = r0 * WW + c0, b01 = r0 * WW + c1;
    int b10 = r1 * WW + c0, b11 = r1 * WW + c1;

    #pragma unroll 4
    for (int ch = 0; ch < 36; ch++) {
        const float* g = x36 + ch * HW;
        float v = wr0 * (wc0 * g[b00] + wc1 * g[b01]) +
                  wr1 * (wc0 * g[b10] + wc1 * g[b11]);
        out[ch * OHW + p] = v;
    }

    const float* s0p = smn;
    const float* s1p = smn + HW;
    float s0 = wr0 * (wc0 * s0p[b00] + wc1 * s0p[b01]) +
               wr1 * (wc0 * s0p[b10] + wc1 * s0p[b11]);
    float s1 = wr0 * (wc0 * s1p[b00] + wc1 * s1p[b01]) +
               wr1 * (wc0 * s1p[b10] + wc1 * s1p[b11]);
    float mu = smask[iy * WW + ix];
    out[36 * OHW + p] = (s0 > s1) ? mu : 0.f;
}

// ---------------------------------------------------------------------------
// Launcher
// ---------------------------------------------------------------------------
extern "C" void kernel_launch(void* const* d_in, const int* in_sizes, int n_in,
                              void* d_out, int out_size)
{
    const float* feat_0     = (const float*)d_in[0];
    const float* feat_1     = (const float*)d_in[1];
    const float* feat_dense = (const float*)d_in[2];
    const float* flow       = (const float*)d_in[3];
    const float* space_mask = (const float*)d_in[4];
    const float* w_head     = (const float*)d_in[5];
    const float* a_head     = (const float*)d_in[6];
    const float* w_blocks   = (const float*)d_in[7];
    const float* a_blocks   = (const float*)d_in[8];
    const float* w_last     = (const float*)d_in[9];
    const float* b_last     = (const float*)d_in[10];
    const float* w_mask     = (const float*)d_in[11];
    const float* b_mask     = (const float*)d_in[12];

    u32 *x0a, *featsa;
    float *x36, *smn;
    __nv_bfloat16* wimg;
    cudaGetSymbolAddress((void**)&x0a,    act2_x0);
    cudaGetSymbolAddress((void**)&featsa, act2_feats);
    cudaGetSymbolAddress((void**)&x36,    g_x36);
    cudaGetSymbolAddress((void**)&smn,    g_smn);
    cudaGetSymbolAddress((void**)&wimg,   g_wimg);

    cudaFuncSetAttribute(conv_hmma_kernel<0>,
                         cudaFuncAttributeMaxDynamicSharedMemorySize, CONV_DSMEM);
    cudaFuncSetAttribute(conv_hmma_kernel<1>,
                         cudaFuncAttributeMaxDynamicSharedMemorySize, CONV_DSMEM);

    prep_weights_kernel<<<45, 256>>>(w_head, w_blocks);
    warp_concat_kernel<<<196, 256>>>(feat_0, feat_1, feat_dense, flow);

    conv_hmma_kernel<0><<<392, 256, CONV_DSMEM>>>(
        x0a, wimg, a_head, space_mask, featsa);
    for (int i = 1; i < 5; i++) {
        conv_hmma_kernel<1><<<392, 256, CONV_DSMEM>>>(
            featsa + (size_t)(i - 1) * HW * 100,
            wimg + (size_t)i * 9 * 30720,
            a_blocks + (i - 1) * 100,
            space_mask,
            featsa + (size_t)i * HW * 100);
    }

    conv1x1_kernel<<<196, 256>>>(featsa, w_last, b_last, x36);

    conv3x3_small_kernel<<<dim3(7, 28, 1), 256>>>(
        x36 + 4 * HW, w_mask, b_mask, smn);

    upsample_kernel<<<784, 256>>>(x36, smn, space_mask, (float*)d_out);
}

// round 8
// speedup vs baseline: 1.0331x; 1.0331x over previous
#include <cuda_runtime.h>
#include <cuda_bf16.h>
#include <cstdint>

#define HH 224
#define WW 224
#define HW (HH*WW)
#define OH 448
#define OW 448
#define OHW (OH*OW)

typedef unsigned int u32;
typedef unsigned long long u64;

// ---------------------------------------------------------------------------
// Scratch: activations pixel-major packed (bf16 hi | bf16 lo<<16)
// ---------------------------------------------------------------------------
__device__ u32  act2_x0[HW * 100];
__device__ u32  act2_feats[5 * HW * 100];
__device__ float g_x36[36 * HW];
__device__ float g_smn[2 * HW];
// weight images: [5 layers][9 kpos][2 splits][112 oc x 120 ci-stride] bf16
__device__ __align__(16) __nv_bfloat16 g_wimg[5 * 9 * 2 * 13440];

// ---------------------------------------------------------------------------
// helpers
// ---------------------------------------------------------------------------
__device__ __forceinline__ u32 smem_u32(const void* p) {
    u32 r;
    asm("{ .reg .u64 t; cvta.to.shared.u64 t, %1; cvt.u32.u64 %0, t; }"
        : "=r"(r) : "l"(p));
    return r;
}
__device__ __forceinline__ void cp16(u32 dst, const void* src) {
    asm volatile("cp.async.cg.shared.global [%0], [%1], 16;"
                 :: "r"(dst), "l"(src));
}
__device__ __forceinline__ void cp_commit() { asm volatile("cp.async.commit_group;"); }
template <int N>
__device__ __forceinline__ void cp_waitN() {
    asm volatile("cp.async.wait_group %0;" :: "n"(N));
}

__device__ __forceinline__ void ldsm4(u32* r, u32 addr) {
    asm volatile("ldmatrix.sync.aligned.m8n8.x4.shared.b16 {%0,%1,%2,%3}, [%4];"
        : "=r"(r[0]), "=r"(r[1]), "=r"(r[2]), "=r"(r[3]) : "r"(addr));
}
__device__ __forceinline__ void mma16816(float* c, const u32* a, u32 b0, u32 b1) {
    asm volatile("mma.sync.aligned.m16n8k16.row.col.f32.bf16.bf16.f32 "
        "{%0,%1,%2,%3}, {%4,%5,%6,%7}, {%8,%9}, {%0,%1,%2,%3};"
        : "+f"(c[0]), "+f"(c[1]), "+f"(c[2]), "+f"(c[3])
        : "r"(a[0]), "r"(a[1]), "r"(a[2]), "r"(a[3]), "r"(b0), "r"(b1));
}

// pack/unpack fp32 <-> (bf16 hi in low16 | bf16 lo in high16)
__device__ __forceinline__ u32 pack_hl(float v) {
    __nv_bfloat16 h = __float2bfloat16(v);
    float fh = __bfloat162float(h);
    __nv_bfloat16 l = __float2bfloat16(v - fh);
    return (u32)__bfloat16_as_ushort(h) | ((u32)__bfloat16_as_ushort(l) << 16);
}
__device__ __forceinline__ float unpack_hl(u32 b) {
    return __uint_as_float(b << 16) + __uint_as_float(b & 0xFFFF0000u);
}

// f32x2
__device__ __forceinline__ u64 pack2f(float lo, float hi) {
    u64 r; asm("mov.b64 %0, {%1, %2};" : "=l"(r) : "f"(lo), "f"(hi)); return r;
}
__device__ __forceinline__ void unpack2f(u64 v, float& lo, float& hi) {
    asm("mov.b64 {%0, %1}, %2;" : "=f"(lo), "=f"(hi) : "l"(v));
}
__device__ __forceinline__ void ffma2(u64& acc, u64 a, u64 b) {
    asm("fma.rn.f32x2 %0, %1, %2, %0;" : "+l"(acc) : "l"(a), "l"(b));
}

// ---------------------------------------------------------------------------
// Prep: weight images. grid = 45 (layer*9 + kpos)
// Per kpos: hi split [112x120] then lo split, row-major, 120-elem ci stride.
// ---------------------------------------------------------------------------
__global__ __launch_bounds__(256) void prep_weights_kernel(
    const float* __restrict__ w_head, const float* __restrict__ w_blocks)
{
    int l = blockIdx.x / 9, kp = blockIdx.x - 9 * (blockIdx.x / 9);
    const float* src = (l == 0) ? w_head : (w_blocks + (l - 1) * 90000);
    __nv_bfloat16* dhi = g_wimg + (size_t)(l * 9 + kp) * 26880;
    __nv_bfloat16* dlo = dhi + 13440;
    for (int i = threadIdx.x; i < 13440; i += 256) {
        int m = i / 120, k = i - 120 * (i / 120);
        float wv = (m < 100 && k < 100) ? src[m * 900 + k * 9 + kp] : 0.f;
        __nv_bfloat16 h = __float2bfloat16(wv);
        __nv_bfloat16 lo = __float2bfloat16(wv - __bfloat162float(h));
        dhi[i] = h;
        dlo[i] = lo;
    }
}

// ---------------------------------------------------------------------------
// Kernel 1: warp + concat -> act2_x0 [p][100]
// ---------------------------------------------------------------------------
__global__ __launch_bounds__(256) void warp_concat_kernel(
    const float* __restrict__ f0, const float* __restrict__ f1,
    const float* __restrict__ fd, const float* __restrict__ flow)
{
    int p = blockIdx.x * 256 + threadIdx.x;
    if (p >= HW) return;
    int y = p / WW, x = p - y * WW;
    u32* row = act2_x0 + (size_t)p * 100;

    #pragma unroll 4
    for (int c = 0; c < 32; c++) row[64 + c] = pack_hl(fd[c * HW + p]);
    #pragma unroll
    for (int c = 0; c < 4; c++)  row[96 + c] = pack_hl(flow[c * HW + p]);

    #pragma unroll
    for (int pair = 0; pair < 2; pair++) {
        const float* img = (pair == 0) ? f0 : f1;
        float px = (float)x + flow[(pair * 2 + 0) * HW + p];
        float py = (float)y + flow[(pair * 2 + 1) * HW + p];
        float fx = floorf(px), fy = floorf(py);
        float wx = px - fx, wy = py - fy;
        int ix = (int)fminf(fmaxf(fx, -2.f), 226.f);
        int iy = (int)fminf(fmaxf(fy, -2.f), 226.f);
        int x0i = min(max(ix, 0), WW - 1);
        int x1i = min(max(ix + 1, 0), WW - 1);
        int y0i = min(max(iy, 0), HH - 1);
        int y1i = min(max(iy + 1, 0), HH - 1);
        float w00 = (1.f - wx) * (1.f - wy);
        float w01 = wx * (1.f - wy);
        float w10 = (1.f - wx) * wy;
        float w11 = wx * wy;
        int b00 = y0i * WW + x0i, b01 = y0i * WW + x1i;
        int b10 = y1i * WW + x0i, b11 = y1i * WW + x1i;
        #pragma unroll 4
        for (int c = 0; c < 32; c++) {
            const float* g = img + c * HW;
            float v = g[b00] * w00 + g[b01] * w01 + g[b10] * w10 + g[b11] * w11;
            row[pair * 32 + c] = pack_hl(v);
        }
    }
}

// ---------------------------------------------------------------------------
// Kernel 2: HMMA implicit-GEMM 3x3 conv.
// CTA: 128 px x 112 oc. 8 warps, each full-M (7 m-tiles) x 16 px (2 nf).
// 4-slot weight ring, prefetch distance 2 (single barrier/kpos, race-free:
// staging at iter kp targets slot (kp+2)&3 == (kp-2)&3 whose readers are
// guaranteed past it by iteration kp-1's barrier). Cross-kpos B prefetch.
// Split bf16 hi/lo, 3 products, fp32 accum.
// ---------------------------------------------------------------------------
#define WSTRIDE 240       // A smem row stride bytes (120 halves)
#define SPLIT_B 26880     // bytes per split
#define KPOS_B  53760     // bytes per kpos stage
#define NSTAGE  4
#define CONV_DSMEM (NSTAGE * KPOS_B)   // 215040 B

__device__ __forceinline__ void loadB2(u32* b, const u32* r0, const u32* r1,
                                       bool ok0, bool ok1, int ci) {
    #pragma unroll
    for (int nf = 0; nf < 2; nf++) {
        const u32* r = nf ? r1 : r0;
        bool ok = nf ? ok1 : ok0;
        u32 v0 = 0, v1 = 0, w0 = 0, w1 = 0;
        if (ok && ci <= 98)     { uint2 t = *(const uint2*)(r + ci);     v0 = t.x; v1 = t.y; }
        if (ok && ci + 8 <= 98) { uint2 t = *(const uint2*)(r + ci + 8); w0 = t.x; w1 = t.y; }
        b[nf * 4 + 0] = __byte_perm(v0, v1, 0x5410);  // hi pair k,k+1
        b[nf * 4 + 1] = __byte_perm(w0, w1, 0x5410);  // hi pair k+8,k+9
        b[nf * 4 + 2] = __byte_perm(v0, v1, 0x7632);  // lo pair
        b[nf * 4 + 3] = __byte_perm(w0, w1, 0x7632);
    }
}

template <int MODE>
__global__ __launch_bounds__(256, 1) void conv_hmma_kernel(
    const u32* __restrict__ in,                 // [HW][100]
    const __nv_bfloat16* __restrict__ wimg,     // layer base, [9][2][13440]
    const float* __restrict__ aux,
    const float* __restrict__ mask,
    u32* __restrict__ outp)                     // [HW][100]
{
    extern __shared__ __align__(16) char dsm[];
    __shared__ float s_mask[128];
    __shared__ float s_aux[112];

    const int tid = threadIdx.x;
    const int w = tid >> 5;
    const int lid = tid & 31;
    const int pixbase = blockIdx.x << 7;

    if (tid < 128) s_mask[tid] = mask[pixbase + tid];
    if (tid < 112) s_aux[tid] = (tid < 100) ? aux[tid] : 0.f;

    const u32 sb = smem_u32(dsm);

    const int p0 = pixbase + w * 16 + (lid >> 2);
    const int p1 = p0 + 8;
    const int py0 = p0 / WW, px0 = p0 - py0 * WW;
    const int py1 = p1 / WW, px1 = p1 - py1 * WW;

    float acc[7][2][4];
    #pragma unroll
    for (int m = 0; m < 7; m++)
        #pragma unroll
        for (int nf = 0; nf < 2; nf++)
            #pragma unroll
            for (int i = 0; i < 4; i++) acc[m][nf][i] = 0.f;

    // prologue: stage kpos 0..1 into slots 0..1 (one commit group each)
    #pragma unroll
    for (int s = 0; s < 2; s++) {
        const char* src = (const char*)wimg + (size_t)s * KPOS_B;
        u32 dst = sb + s * KPOS_B;
        for (int i = tid; i < 3360; i += 256) cp16(dst + i * 16, src + i * 16);
        cp_commit();
    }

    const int cib = (lid & 3) * 2;
    const u32 arow = (lid & 15) * WSTRIDE + (lid >> 4) * 16;

    // row pointers for a given kpos
    auto rowsFor = [&](int kp, const u32*& r0, const u32*& r1,
                       bool& ok0, bool& ok1) {
        int ky = kp / 3 - 1, kx = kp - 3 * (kp / 3) - 1;
        int iy0 = py0 + ky, ix0 = px0 + kx;
        int iy1 = py1 + ky, ix1 = px1 + kx;
        ok0 = (iy0 >= 0) & (iy0 < HH) & (ix0 >= 0) & (ix0 < WW);
        ok1 = (iy1 >= 0) & (iy1 < HH) & (ix1 >= 0) & (ix1 < WW);
        r0 = in + (size_t)(iy0 * WW + ix0) * 100;
        r1 = in + (size_t)(iy1 * WW + ix1) * 100;
    };

    const u32 *rc0, *rc1, *rn0, *rn1;
    bool okc0, okc1, okn0, okn1;
    rowsFor(0, rc0, rc1, okc0, okc1);

    // initial B fragments (kp=0, ks=0) — issued before any weight wait
    u32 bc[8], bn[8];
    loadB2(bc, rc0, rc1, okc0, okc1, cib);

    for (int kp = 0; kp < 9; kp++) {
        const u32 bufaddr = sb + (kp & 3) * KPOS_B;

        if (kp + 2 < 9) {   // stage kpos kp+2 into ring slot (distance 2: safe)
            const char* src = (const char*)wimg + (size_t)(kp + 2) * KPOS_B;
            u32 dst = sb + ((kp + 2) & 3) * KPOS_B;
            for (int i = tid; i < 3360; i += 256) cp16(dst + i * 16, src + i * 16);
            cp_commit();
        }
        // wait until stage kp is complete (<= pending groups remain)
        if (kp <= 6)      cp_waitN<2>();
        else if (kp == 7) cp_waitN<1>();
        else              cp_waitN<0>();
        __syncthreads();   // single barrier per kpos

        // next-kpos rows (for cross-boundary B prefetch)
        if (kp < 8) rowsFor(kp + 1, rn0, rn1, okn0, okn1);

        #pragma unroll
        for (int ks = 0; ks < 7; ks++) {
            // prefetch next kstep's B (crosses kpos boundary at ks==6)
            if (ks < 6)
                loadB2(bn, rc0, rc1, okc0, okc1, cib + (ks + 1) * 16);
            else if (kp < 8)
                loadB2(bn, rn0, rn1, okn0, okn1, cib);

            const u32 kaddr = bufaddr + arow + ks * 32;
            #pragma unroll
            for (int m = 0; m < 7; m++) {
                u32 ah[4], al[4];
                ldsm4(ah, kaddr + m * 3840);
                ldsm4(al, kaddr + m * 3840 + SPLIT_B);
                #pragma unroll
                for (int nf = 0; nf < 2; nf++) {
                    mma16816(acc[m][nf], ah, bc[nf * 4 + 0], bc[nf * 4 + 1]); // hh
                    mma16816(acc[m][nf], ah, bc[nf * 4 + 2], bc[nf * 4 + 3]); // h*l
                    mma16816(acc[m][nf], al, bc[nf * 4 + 0], bc[nf * 4 + 1]); // l*h
                }
            }
            #pragma unroll
            for (int q = 0; q < 8; q++) bc[q] = bn[q];
        }
        // advance current rows
        rc0 = rn0; rc1 = rn1; okc0 = okn0; okc1 = okn1;
    }
    __syncthreads();   // protect dsm reuse by epilogue

    // epilogue: transform + smem transpose + coalesced store
    u32* tr = (u32*)dsm;      // [128 px][stride 116] u32
    #pragma unroll
    for (int m = 0; m < 7; m++) {
        const int oc0 = m * 16 + (lid >> 2);
        #pragma unroll
        for (int nf = 0; nf < 2; nf++) {
            const int pxc = w * 16 + nf * 8 + (lid & 3) * 2;
            #pragma unroll
            for (int i = 0; i < 4; i++) {
                const int oc = oc0 + (i >> 1) * 8;
                const int px = pxc + (i & 1);
                if (oc < 100) {
                    float v = acc[m][nf][i];
                    float a = s_aux[oc], mm = s_mask[px];
                    if (MODE == 0) {
                        v = (v >= 0.f ? v : a * v) * mm;
                    } else {
                        v *= mm;
                        v = (v >= 0.f ? v : a * v);
                    }
                    tr[px * 116 + oc] = pack_hl(v);
                }
            }
        }
    }
    __syncthreads();
    for (int i = tid; i < 12800; i += 256) {
        int px = i / 100, ci = i - 100 * (i / 100);
        outp[(size_t)(pixbase + px) * 100 + ci] = tr[px * 116 + ci];
    }
}

// ---------------------------------------------------------------------------
// Kernel 3: 1x1 conv 500 -> 36, f32x2, pixel-major packed input
// ---------------------------------------------------------------------------
__global__ __launch_bounds__(256) void conv1x1_kernel(
    const u32* __restrict__ feats, const float* __restrict__ wl,
    const float* __restrict__ bl, float* __restrict__ out)
{
    __shared__ __align__(16) float s_w[3600];
    const int tid = threadIdx.x;
    const size_t p = (size_t)blockIdx.x * 256 + tid;

    u64 acc[18];
    #pragma unroll
    for (int pr = 0; pr < 18; pr++) acc[pr] = pack2f(bl[pr * 2], bl[pr * 2 + 1]);

    for (int ch = 0; ch < 5; ch++) {
        __syncthreads();
        for (int i = tid; i < 3600; i += 256) {
            int ci = i / 36, o = i - ci * 36;
            s_w[(ci * 18 + (o >> 1)) * 2 + (o & 1)] = wl[o * 500 + ch * 100 + ci];
        }
        __syncthreads();
        const uint4* row = (const uint4*)(feats + ((size_t)ch * HW + p) * 100);
        #pragma unroll 5
        for (int g = 0; g < 25; g++) {
            uint4 q = row[g];
            u32 vv[4] = {q.x, q.y, q.z, q.w};
            #pragma unroll
            for (int j = 0; j < 4; j++) {
                float f = unpack_hl(vv[j]);
                u64 f2 = pack2f(f, f);
                const u64* wp = (const u64*)(s_w + (g * 4 + j) * 36);
                #pragma unroll
                for (int pr = 0; pr < 18; pr++) ffma2(acc[pr], wp[pr], f2);
            }
        }
    }
    #pragma unroll
    for (int pr = 0; pr < 18; pr++) {
        float v0, v1;
        unpack2f(acc[pr], v0, v1);
        out[(pr * 2 + 0) * HW + p] = v0;
        out[(pr * 2 + 1) * HW + p] = v1;
    }
}

// ---------------------------------------------------------------------------
// Kernel 2b: small 3x3 conv (mask head), 32 -> 2, bias
// ---------------------------------------------------------------------------
__global__ __launch_bounds__(256) void conv3x3_small_kernel(
    const float* __restrict__ in, const float* __restrict__ wgt,
    const float* __restrict__ bias, float* __restrict__ out)
{
    __shared__ float s_in[10 * 34];
    __shared__ float s_w[2 * 9];

    const int tid = threadIdx.x;
    const int tx = tid & 31;
    const int ty = tid >> 5;
    const int ox0 = blockIdx.x * 32;
    const int oy0 = blockIdx.y * 8;
    const int ox = ox0 + tx, oy = oy0 + ty;

    float acc0 = 0.f, acc1 = 0.f;

    for (int ci = 0; ci < 32; ci++) {
        #pragma unroll
        for (int idx = tid; idx < 340; idx += 256) {
            int r = idx / 34, c = idx - r * 34;
            int gy = oy0 - 1 + r, gx = ox0 - 1 + c;
            float v = 0.f;
            if (gx >= 0 && gx < WW && gy >= 0 && gy < HH)
                v = in[ci * HW + gy * WW + gx];
            s_in[idx] = v;
        }
        if (tid < 18)
            s_w[tid] = wgt[(tid / 9) * (32 * 9) + ci * 9 + (tid % 9)];
        __syncthreads();

        float r[9];
        #pragma unroll
        for (int ky = 0; ky < 3; ky++)
            #pragma unroll
            for (int kx = 0; kx < 3; kx++)
                r[ky * 3 + kx] = s_in[(ty + ky) * 34 + tx + kx];

        #pragma unroll
        for (int k = 0; k < 9; k++) {
            acc0 = fmaf(s_w[k], r[k], acc0);
            acc1 = fmaf(s_w[9 + k], r[k], acc1);
        }
        __syncthreads();
    }
    out[oy * WW + ox] = acc0 + bias[0];
    out[HW + oy * WW + ox] = acc1 + bias[1];
}

// ---------------------------------------------------------------------------
// Kernel 4: 2x bilinear upsample + mask
// ---------------------------------------------------------------------------
__global__ __launch_bounds__(256) void upsample_kernel(
    const float* __restrict__ x36, const float* __restrict__ smn,
    const float* __restrict__ smask, float* __restrict__ out)
{
    int p = blockIdx.x * 256 + threadIdx.x;
    if (p >= OHW) return;
    int oy = p / OW, ox = p - oy * OW;
    int iy = oy >> 1, ix = ox >> 1;

    int r0, r1; float wr0, wr1;
    if (oy & 1) { r0 = iy; r1 = min(iy + 1, HH - 1); wr0 = 0.75f; wr1 = 0.25f; }
    else        { r0 = max(iy - 1, 0); r1 = iy;      wr0 = 0.25f; wr1 = 0.75f; }
    int c0, c1; float wc0, wc1;
    if (ox & 1) { c0 = ix; c1 = min(ix + 1, WW - 1); wc0 = 0.75f; wc1 = 0.25f; }
    else        { c0 = max(ix - 1, 0); c1 = ix;      wc0 = 0.25f; wc1 = 0.75f; }

    int b00 = r0 * WW + c0, b01 = r0 * WW + c1;
    int b10 = r1 * WW + c0, b11 = r1 * WW + c1;

    #pragma unroll 4
    for (int ch = 0; ch < 36; ch++) {
        const float* g = x36 + ch * HW;
        float v = wr0 * (wc0 * g[b00] + wc1 * g[b01]) +
                  wr1 * (wc0 * g[b10] + wc1 * g[b11]);
        out[ch * OHW + p] = v;
    }

    const float* s0p = smn;
    const float* s1p = smn + HW;
    float s0 = wr0 * (wc0 * s0p[b00] + wc1 * s0p[b01]) +
               wr1 * (wc0 * s0p[b10] + wc1 * s0p[b11]);
    float s1 = wr0 * (wc0 * s1p[b00] + wc1 * s1p[b01]) +
               wr1 * (wc0 * s1p[b10] + wc1 * s1p[b11]);
    float mu = smask[iy * WW + ix];
    out[36 * OHW + p] = (s0 > s1) ? mu : 0.f;
}

// ---------------------------------------------------------------------------
// Launcher
// ---------------------------------------------------------------------------
extern "C" void kernel_launch(void* const* d_in, const int* in_sizes, int n_in,
                              void* d_out, int out_size)
{
    const float* feat_0     = (const float*)d_in[0];
    const float* feat_1     = (const float*)d_in[1];
    const float* feat_dense = (const float*)d_in[2];
    const float* flow       = (const float*)d_in[3];
    const float* space_mask = (const float*)d_in[4];
    const float* w_head     = (const float*)d_in[5];
    const float* a_head     = (const float*)d_in[6];
    const float* w_blocks   = (const float*)d_in[7];
    const float* a_blocks   = (const float*)d_in[8];
    const float* w_last     = (const float*)d_in[9];
    const float* b_last     = (const float*)d_in[10];
    const float* w_mask     = (const float*)d_in[11];
    const float* b_mask     = (const float*)d_in[12];

    u32 *x0a, *featsa;
    float *x36, *smn;
    __nv_bfloat16* wimg;
    cudaGetSymbolAddress((void**)&x0a,    act2_x0);
    cudaGetSymbolAddress((void**)&featsa, act2_feats);
    cudaGetSymbolAddress((void**)&x36,    g_x36);
    cudaGetSymbolAddress((void**)&smn,    g_smn);
    cudaGetSymbolAddress((void**)&wimg,   g_wimg);

    cudaFuncSetAttribute(conv_hmma_kernel<0>,
                         cudaFuncAttributeMaxDynamicSharedMemorySize, CONV_DSMEM);
    cudaFuncSetAttribute(conv_hmma_kernel<1>,
                         cudaFuncAttributeMaxDynamicSharedMemorySize, CONV_DSMEM);

    prep_weights_kernel<<<45, 256>>>(w_head, w_blocks);
    warp_concat_kernel<<<196, 256>>>(feat_0, feat_1, feat_dense, flow);

    conv_hmma_kernel<0><<<392, 256, CONV_DSMEM>>>(
        x0a, wimg, a_head, space_mask, featsa);
    for (int i = 1; i < 5; i++) {
        conv_hmma_kernel<1><<<392, 256, CONV_DSMEM>>>(
            featsa + (size_t)(i - 1) * HW * 100,
            wimg + (size_t)i * 9 * 26880,
            a_blocks + (i - 1) * 100,
            space_mask,
            featsa + (size_t)i * HW * 100);
    }

    conv1x1_kernel<<<196, 256>>>(featsa, w_last, b_last, x36);

    conv3x3_small_kernel<<<dim3(7, 28, 1), 256>>>(
        x36 + 4 * HW, w_mask, b_mask, smn);

    upsample_kernel<<<784, 256>>>(x36, smn, space_mask, (float*)d_out);
}